// round 15
// baseline (speedup 1.0000x reference)
#include <cuda_runtime.h>
#include <math.h>

#define PB   128          // time groups == prep blocks (all co-resident)
#define SPB  16           // steps per group; PB*SPB == 2048
#define NTH  512
#define W2_BYTES (128 * 128 * sizeof(float))

__device__ float g_csum[16 * PB];      // per-group per-component sums
__device__ unsigned g_flag[PB];        // csum epoch flags (replay-safe)
__device__ unsigned g_Eflag[PB];       // per-group E-ready epoch flags
__device__ unsigned g_epoch;           // current epoch, published to apply
__device__ float g_E[PB * SPB * 16];   // expm(cumsum)

__device__ __forceinline__ float tanh_fast(float v) {
    float y;
    asm("tanh.approx.f32 %0, %1;" : "=f"(y) : "f"(v));
    return y;
}

// ---------------------------------------------------------------------------
// Prep: early PDL trigger -> MLP -> csum flags -> scan -> expm -> per-group
// E-ready flag. Apply overlaps with everything after the early trigger.
// ---------------------------------------------------------------------------
__global__ void __launch_bounds__(NTH, 1)
prep_kernel(const float* __restrict__ t,
            const float* __restrict__ M0,
            const float* __restrict__ W1, const float* __restrict__ b1,
            const float* __restrict__ W2, const float* __restrict__ b2,
            const float* __restrict__ W3, const float* __restrict__ b3,
            int T) {
    int b   = blockIdx.x;
    int tid = threadIdx.x;

    extern __shared__ float W2s[];   // 64 KB

    __shared__ float h1s[SPB * 128];
    __shared__ float h2s[SPB * 128];
    __shared__ float W3s[128 * 16];
    __shared__ float tavg[SPB], dts[SPB];
    __shared__ float As[SPB * 16];      // [s][p] A, then cumsum
    __shared__ float Es[SPB * 16];      // expm results
    __shared__ unsigned target_sh;

    if (tid == 0) {
        unsigned tgt = atomicAdd(&g_flag[b], 0u) + 1u;
        target_sh = tgt;
        if (b == 0) {
            g_epoch = tgt;           // publish epoch for the apply grid
            __threadfence();
        }
    }

    {
        const float4* src = (const float4*)W2;
        float4* dst = (float4*)W2s;
#pragma unroll
        for (int idx = tid; idx < 128 * 32; idx += NTH) dst[idx] = src[idx];
    }

    if (tid < SPB) {
        int i = b * SPB + tid;
        float tc = (i < T) ? t[i] : 1.0f;
        float tp = (i == 0) ? 0.0f : ((i - 1 < T) ? t[i - 1] : 1.0f);
        dts[tid]  = tc - tp;
        tavg[tid] = 0.5f * (tc + tp);
    }
    for (int idx = tid; idx < 128 * 16; idx += NTH) W3s[idx] = W3[idx];
    __syncthreads();

    // EARLY PDL trigger: epoch is published (and visible per PDL semantics);
    // apply grid may launch now and overlap with the MLP/scan/expm below.
    asm volatile("griddepcontrol.launch_dependents;");

    // layer 1
    for (int idx = tid; idx < SPB * 128; idx += NTH) {
        int s = idx >> 7, k = idx & 127;
        h1s[idx] = tanh_fast(tavg[s] * W1[k] + b1[k]);
    }
    __syncthreads();

    // layer 2
    {
        int j  = tid & 127;
        int sg = (tid >> 7) * 4;
        float bb = b2[j];
        float a0 = bb, a1 = bb, a2 = bb, a3 = bb;
#pragma unroll 8
        for (int k = 0; k < 128; k++) {
            float w = W2s[k * 128 + j];
            a0 = fmaf(w, h1s[(sg + 0) * 128 + k], a0);
            a1 = fmaf(w, h1s[(sg + 1) * 128 + k], a1);
            a2 = fmaf(w, h1s[(sg + 2) * 128 + k], a2);
            a3 = fmaf(w, h1s[(sg + 3) * 128 + k], a3);
        }
        h2s[(sg + 0) * 128 + j] = tanh_fast(a0);
        h2s[(sg + 1) * 128 + j] = tanh_fast(a1);
        h2s[(sg + 2) * 128 + j] = tanh_fast(a2);
        h2s[(sg + 3) * 128 + j] = tanh_fast(a3);
    }
    __syncthreads();

    // layer 3
    if (tid < SPB * 16) {
        int s = tid >> 4;
        int p = tid & 15;
        float a0 = b3[p], a1 = 0.f, a2 = 0.f, a3 = 0.f;
#pragma unroll 8
        for (int k = 0; k < 128; k += 4) {
            a0 = fmaf(h2s[s * 128 + k + 0], W3s[(k + 0) * 16 + p], a0);
            a1 = fmaf(h2s[s * 128 + k + 1], W3s[(k + 1) * 16 + p], a1);
            a2 = fmaf(h2s[s * 128 + k + 2], W3s[(k + 2) * 16 + p], a2);
            a3 = fmaf(h2s[s * 128 + k + 3], W3s[(k + 3) * 16 + p], a3);
        }
        As[tid] = ((a0 + a1) + (a2 + a3) + M0[p]) * dts[s];
    }
    __syncthreads();

    // publish chunk sums + csum epoch flag
    if (tid < 16) {
        int c = tid;
        float sum = 0.0f;
#pragma unroll
        for (int e = 0; e < SPB; e++) {
            int i = b * SPB + e;
            if (i < T) sum += As[e * 16 + c];
        }
        g_csum[c * PB + b] = sum;
    }
    __syncthreads();
    unsigned target = target_sh;
    if (tid == 0) {
        __threadfence();
        atomicExch(&g_flag[b], target);
    }

    // wait for predecessors 0..b-1
    if (tid < b) {
        while (atomicAdd(&g_flag[tid], 0u) < target) { }
    }
    __syncthreads();
    __threadfence();

    // offsets
    __shared__ float off[16];
    {
        int c = tid >> 4, l = tid & 15;
        if (c < 16) {
            float v = 0.0f;
            for (int q = l; q < b; q += 16) v += g_csum[c * PB + q];
            v += __shfl_down_sync(0xffffffffu, v, 8);
            v += __shfl_down_sync(0xffffffffu, v, 4);
            v += __shfl_down_sync(0xffffffffu, v, 2);
            v += __shfl_down_sync(0xffffffffu, v, 1);
            if (l == 0) off[c] = v;
        }
    }
    __syncthreads();

    // local inclusive scan
    if (tid < 16) {
        int c = tid;
        float run = off[c];
#pragma unroll
        for (int e = 0; e < SPB; e++) {
            run += As[e * 16 + c];
            As[e * 16 + c] = run;
        }
    }
    __syncthreads();

    // expm: threads 0..15, one matrix each -> Es
    if (tid < SPB) {
        float a[16];
#pragma unroll
        for (int p = 0; p < 16; p++) a[p] = As[tid * 16 + p];

        float nrm = 0.0f;
#pragma unroll
        for (int r = 0; r < 4; r++) {
            float rs = fabsf(a[r*4]) + fabsf(a[r*4+1]) + fabsf(a[r*4+2]) + fabsf(a[r*4+3]);
            nrm = fmaxf(nrm, rs);
        }
        int sq = 0;
        while (nrm > 0.5f && sq < 40) { nrm *= 0.5f; sq++; }
        float sc = ldexpf(1.0f, -sq);
#pragma unroll
        for (int p = 0; p < 16; p++) a[p] *= sc;

        float P[16], E[16];
#pragma unroll
        for (int p = 0; p < 16; p++) { P[p] = a[p]; E[p] = a[p]; }
#pragma unroll
        for (int d = 0; d < 4; d++) E[d * 5] += 1.0f;

        for (int k = 2; k <= 10; k++) {
            float Q[16];
            float inv = 1.0f / (float)k;
#pragma unroll
            for (int r = 0; r < 4; r++)
#pragma unroll
                for (int c = 0; c < 4; c++)
                    Q[r*4+c] = (P[r*4+0]*a[0*4+c] + P[r*4+1]*a[1*4+c]
                              + P[r*4+2]*a[2*4+c] + P[r*4+3]*a[3*4+c]) * inv;
#pragma unroll
            for (int p = 0; p < 16; p++) { P[p] = Q[p]; E[p] += Q[p]; }
        }
        for (int q = 0; q < sq; q++) {
            float Q[16];
#pragma unroll
            for (int r = 0; r < 4; r++)
#pragma unroll
                for (int c = 0; c < 4; c++)
                    Q[r*4+c] = E[r*4+0]*E[0*4+c] + E[r*4+1]*E[1*4+c]
                             + E[r*4+2]*E[2*4+c] + E[r*4+3]*E[3*4+c];
#pragma unroll
            for (int p = 0; p < 16; p++) E[p] = Q[p];
        }
#pragma unroll
        for (int p = 0; p < 16; p++) Es[tid * 16 + p] = E[p];
    }
    __syncthreads();

    // coalesced g_E write, then signal this group ready
    if (tid < SPB * 16) {
        int i = b * SPB + (tid >> 4);
        if (i < T) g_E[i * 16 + (tid & 15)] = Es[tid];
    }
    __syncthreads();
    if (tid == 0) {
        __threadfence();
        atomicExch(&g_Eflag[b], target);
    }
}

// ---------------------------------------------------------------------------
// Apply: PDL secondary, launched early; each block spin-waits only on ITS
// time group's E-ready flag, then streams 64 KB of __stcs stores.
// ---------------------------------------------------------------------------
#define TT 16
__global__ void __launch_bounds__(256)
apply_kernel(const float* __restrict__ x,
             float4* __restrict__ out,
             int N, int T) {
    int g     = blockIdx.y;           // time group (TT == SPB)
    int tbase = g * TT;
    int n = blockIdx.x * blockDim.x + threadIdx.x;

    // prep-independent work first
    float4 xv = make_float4(0.f, 0.f, 0.f, 0.f);
    if (n < N) xv = __ldg((const float4*)x + n);

    // PDL: ensures g_epoch (written before launch_dependents) is visible
    asm volatile("griddepcontrol.wait;" ::: "memory");

    // wait for this group's E to be published (monotonic epoch)
    if (threadIdx.x == 0) {
        unsigned tgt = atomicAdd(&g_epoch, 0u);
        while (atomicAdd(&g_Eflag[g], 0u) < tgt) { __nanosleep(64); }
        __threadfence();
    }
    __syncthreads();

    __shared__ float Es[TT * 16];
    int nt = T - tbase; if (nt > TT) nt = TT;
    if (threadIdx.x < nt * 16) Es[threadIdx.x] = g_E[tbase * 16 + threadIdx.x];
    __syncthreads();

    if (n >= N) return;

#pragma unroll
    for (int k = 0; k < TT; k++) {
        if (k >= nt) break;
        const float* e = &Es[k * 16];
        float4 o;
        o.x = e[0]  * xv.x + e[1]  * xv.y + e[2]  * xv.z + e[3]  * xv.w;
        o.y = e[4]  * xv.x + e[5]  * xv.y + e[6]  * xv.z + e[7]  * xv.w;
        o.z = e[8]  * xv.x + e[9]  * xv.y + e[10] * xv.z + e[11] * xv.w;
        o.w = e[12] * xv.x + e[13] * xv.y + e[14] * xv.z + e[15] * xv.w;
        __stcs(&out[(size_t)(tbase + k) * N + n], o);
    }
}

// ---------------------------------------------------------------------------
extern "C" void kernel_launch(void* const* d_in, const int* in_sizes, int n_in,
                              void* d_out, int out_size) {
    const float* x  = (const float*)d_in[0];
    const float* t  = (const float*)d_in[1];
    const float* M0 = (const float*)d_in[2];
    const float* W1 = (const float*)d_in[3];
    const float* b1 = (const float*)d_in[4];
    const float* W2 = (const float*)d_in[5];
    const float* b2 = (const float*)d_in[6];
    const float* W3 = (const float*)d_in[7];
    const float* b3 = (const float*)d_in[8];
    float* out = (float*)d_out;

    int N = in_sizes[0] / 4;
    int T = in_sizes[1];    // <= PB*SPB (2048)

    static bool attr_set = false;
    if (!attr_set) {
        cudaFuncSetAttribute(prep_kernel,
                             cudaFuncAttributeMaxDynamicSharedMemorySize,
                             W2_BYTES);
        attr_set = true;
    }

    prep_kernel<<<PB, NTH, W2_BYTES>>>(t, M0, W1, b1, W2, b2, W3, b3, T);

    cudaLaunchConfig_t cfg = {};
    cfg.gridDim  = dim3((N + 255) / 256, (T + TT - 1) / TT, 1);
    cfg.blockDim = dim3(256, 1, 1);
    cfg.dynamicSmemBytes = 0;
    cfg.stream = 0;
    cudaLaunchAttribute attrs[1];
    attrs[0].id = cudaLaunchAttributeProgrammaticStreamSerialization;
    attrs[0].val.programmaticStreamSerializationAllowed = 1;
    cfg.attrs = attrs;
    cfg.numAttrs = 1;

    cudaLaunchKernelEx(&cfg, apply_kernel, x, (float4*)out, N, T);
}

// round 16
// speedup vs baseline: 1.0006x; 1.0006x over previous
#include <cuda_runtime.h>
#include <math.h>

#define PB   256          // time groups == prep blocks (2/SM co-resident)
#define SPB  8            // steps per group; PB*SPB == 2048
#define NTH  256
#define W2_BYTES (128 * 128 * sizeof(float))

__device__ float g_csum[16 * PB];      // per-group per-component sums
__device__ unsigned g_flag[PB];        // csum epoch flags (replay-safe)
__device__ float g_E[PB * SPB * 16];   // expm(cumsum)

__device__ __forceinline__ float tanh_fast(float v) {
    float y;
    asm("tanh.approx.f32 %0, %1;" : "=f"(y) : "f"(v));
    return y;
}

// ---------------------------------------------------------------------------
// Prep: MLP -> A (SMEM) -> publish csum+flag -> wait preds -> offsets ->
// local scan -> expm -> g_E -> PDL trigger (at END — R15 proved early
// overlap loses to contention).
// ---------------------------------------------------------------------------
__global__ void __launch_bounds__(NTH, 2)
prep_kernel(const float* __restrict__ t,
            const float* __restrict__ M0,
            const float* __restrict__ W1, const float* __restrict__ b1,
            const float* __restrict__ W2, const float* __restrict__ b2,
            const float* __restrict__ W3, const float* __restrict__ b3,
            int T) {
    int b   = blockIdx.x;
    int tid = threadIdx.x;

    extern __shared__ float W2s[];   // 64 KB

    __shared__ float h1s[SPB * 128];
    __shared__ float h2s[SPB * 128];
    __shared__ float W3s[128 * 16];
    __shared__ float tavg[SPB], dts[SPB];
    __shared__ float As[SPB * 16];      // [s][p] A, then cumsum
    __shared__ float Es[SPB * 16];      // expm results
    __shared__ unsigned target_sh;

    if (tid == 0) target_sh = atomicAdd(&g_flag[b], 0u) + 1u;

    {
        const float4* src = (const float4*)W2;
        float4* dst = (float4*)W2s;
#pragma unroll
        for (int idx = tid; idx < 128 * 32; idx += NTH) dst[idx] = src[idx];
    }

    if (tid < SPB) {
        int i = b * SPB + tid;
        float tc = (i < T) ? t[i] : 1.0f;
        float tp = (i == 0) ? 0.0f : ((i - 1 < T) ? t[i - 1] : 1.0f);
        dts[tid]  = tc - tp;
        tavg[tid] = 0.5f * (tc + tp);
    }
    for (int idx = tid; idx < 128 * 16; idx += NTH) W3s[idx] = W3[idx];
    __syncthreads();

    // layer 1: SPB*128 = 1024 values
    for (int idx = tid; idx < SPB * 128; idx += NTH) {
        int s = idx >> 7, k = idx & 127;
        h1s[idx] = tanh_fast(tavg[s] * W1[k] + b1[k]);
    }
    __syncthreads();

    // layer 2: thread = output j (tid&127), step group (tid>>7)*4 (0 or 4)
    {
        int j  = tid & 127;
        int sg = (tid >> 7) * 4;
        float bb = b2[j];
        float a0 = bb, a1 = bb, a2 = bb, a3 = bb;
#pragma unroll 8
        for (int k = 0; k < 128; k++) {
            float w = W2s[k * 128 + j];
            a0 = fmaf(w, h1s[(sg + 0) * 128 + k], a0);
            a1 = fmaf(w, h1s[(sg + 1) * 128 + k], a1);
            a2 = fmaf(w, h1s[(sg + 2) * 128 + k], a2);
            a3 = fmaf(w, h1s[(sg + 3) * 128 + k], a3);
        }
        h2s[(sg + 0) * 128 + j] = tanh_fast(a0);
        h2s[(sg + 1) * 128 + j] = tanh_fast(a1);
        h2s[(sg + 2) * 128 + j] = tanh_fast(a2);
        h2s[(sg + 3) * 128 + j] = tanh_fast(a3);
    }
    __syncthreads();

    // layer 3: SPB*16 = 128 outputs, one per thread
    if (tid < SPB * 16) {
        int s = tid >> 4;
        int p = tid & 15;
        float a0 = b3[p], a1 = 0.f, a2 = 0.f, a3 = 0.f;
#pragma unroll 8
        for (int k = 0; k < 128; k += 4) {
            a0 = fmaf(h2s[s * 128 + k + 0], W3s[(k + 0) * 16 + p], a0);
            a1 = fmaf(h2s[s * 128 + k + 1], W3s[(k + 1) * 16 + p], a1);
            a2 = fmaf(h2s[s * 128 + k + 2], W3s[(k + 2) * 16 + p], a2);
            a3 = fmaf(h2s[s * 128 + k + 3], W3s[(k + 3) * 16 + p], a3);
        }
        As[tid] = ((a0 + a1) + (a2 + a3) + M0[p]) * dts[s];
    }
    __syncthreads();

    // publish chunk sums + epoch flag
    if (tid < 16) {
        int c = tid;
        float sum = 0.0f;
#pragma unroll
        for (int e = 0; e < SPB; e++) {
            int i = b * SPB + e;
            if (i < T) sum += As[e * 16 + c];
        }
        g_csum[c * PB + b] = sum;
    }
    __syncthreads();
    unsigned target = target_sh;
    if (tid == 0) {
        __threadfence();
        atomicExch(&g_flag[b], target);
    }

    // wait for predecessors 0..b-1 (threads poll distinct flags; two rounds
    // since b can reach 255 with only 256 threads)
    for (int q = tid; q < b; q += NTH) {
        while (atomicAdd(&g_flag[q], 0u) < target) { }
    }
    __syncthreads();
    __threadfence();

    // offsets: 16 lanes per component over predecessors
    __shared__ float off[16];
    {
        int c = tid >> 4, l = tid & 15;
        if (c < 16) {
            float v = 0.0f;
            for (int q = l; q < b; q += 16) v += g_csum[c * PB + q];
            v += __shfl_down_sync(0xffffffffu, v, 8);
            v += __shfl_down_sync(0xffffffffu, v, 4);
            v += __shfl_down_sync(0xffffffffu, v, 2);
            v += __shfl_down_sync(0xffffffffu, v, 1);
            if (l == 0) off[c] = v;
        }
    }
    __syncthreads();

    // local inclusive scan
    if (tid < 16) {
        int c = tid;
        float run = off[c];
#pragma unroll
        for (int e = 0; e < SPB; e++) {
            run += As[e * 16 + c];
            As[e * 16 + c] = run;
        }
    }
    __syncthreads();

    // expm: threads 0..SPB-1, one matrix each -> Es
    if (tid < SPB) {
        float a[16];
#pragma unroll
        for (int p = 0; p < 16; p++) a[p] = As[tid * 16 + p];

        float nrm = 0.0f;
#pragma unroll
        for (int r = 0; r < 4; r++) {
            float rs = fabsf(a[r*4]) + fabsf(a[r*4+1]) + fabsf(a[r*4+2]) + fabsf(a[r*4+3]);
            nrm = fmaxf(nrm, rs);
        }
        int sq = 0;
        while (nrm > 0.5f && sq < 40) { nrm *= 0.5f; sq++; }
        float sc = ldexpf(1.0f, -sq);
#pragma unroll
        for (int p = 0; p < 16; p++) a[p] *= sc;

        float P[16], E[16];
#pragma unroll
        for (int p = 0; p < 16; p++) { P[p] = a[p]; E[p] = a[p]; }
#pragma unroll
        for (int d = 0; d < 4; d++) E[d * 5] += 1.0f;

        for (int k = 2; k <= 10; k++) {
            float Q[16];
            float inv = 1.0f / (float)k;
#pragma unroll
            for (int r = 0; r < 4; r++)
#pragma unroll
                for (int c = 0; c < 4; c++)
                    Q[r*4+c] = (P[r*4+0]*a[0*4+c] + P[r*4+1]*a[1*4+c]
                              + P[r*4+2]*a[2*4+c] + P[r*4+3]*a[3*4+c]) * inv;
#pragma unroll
            for (int p = 0; p < 16; p++) { P[p] = Q[p]; E[p] += Q[p]; }
        }
        for (int q = 0; q < sq; q++) {
            float Q[16];
#pragma unroll
            for (int r = 0; r < 4; r++)
#pragma unroll
                for (int c = 0; c < 4; c++)
                    Q[r*4+c] = E[r*4+0]*E[0*4+c] + E[r*4+1]*E[1*4+c]
                             + E[r*4+2]*E[2*4+c] + E[r*4+3]*E[3*4+c];
#pragma unroll
            for (int p = 0; p < 16; p++) E[p] = Q[p];
        }
#pragma unroll
        for (int p = 0; p < 16; p++) Es[tid * 16 + p] = E[p];
    }
    __syncthreads();

    // coalesced g_E write
    if (tid < SPB * 16) {
        int i = b * SPB + (tid >> 4);
        if (i < T) g_E[i * 16 + (tid & 15)] = Es[tid];
    }
    __syncthreads();
    __threadfence();

    // PDL: allow dependent (apply) grid to launch now
    asm volatile("griddepcontrol.launch_dependents;");
}

// ---------------------------------------------------------------------------
// Apply (heavy, R14 exact): out[t,n,:] = E[t] @ x[n,:]. All __stcs.
// ---------------------------------------------------------------------------
#define TT 16
__global__ void __launch_bounds__(256)
apply_kernel(const float* __restrict__ x,
             float4* __restrict__ out,
             int N, int T) {
    int tbase = blockIdx.y * TT;
    int n = blockIdx.x * blockDim.x + threadIdx.x;

    // prep-independent work first
    float4 xv = make_float4(0.f, 0.f, 0.f, 0.f);
    if (n < N) xv = __ldg((const float4*)x + n);

    asm volatile("griddepcontrol.wait;" ::: "memory");

    __shared__ float Es[TT * 16];
    int nt = T - tbase; if (nt > TT) nt = TT;
    if (threadIdx.x < nt * 16) Es[threadIdx.x] = g_E[tbase * 16 + threadIdx.x];
    __syncthreads();

    if (n >= N) return;

#pragma unroll
    for (int k = 0; k < TT; k++) {
        if (k >= nt) break;
        const float* e = &Es[k * 16];
        float4 o;
        o.x = e[0]  * xv.x + e[1]  * xv.y + e[2]  * xv.z + e[3]  * xv.w;
        o.y = e[4]  * xv.x + e[5]  * xv.y + e[6]  * xv.z + e[7]  * xv.w;
        o.z = e[8]  * xv.x + e[9]  * xv.y + e[10] * xv.z + e[11] * xv.w;
        o.w = e[12] * xv.x + e[13] * xv.y + e[14] * xv.z + e[15] * xv.w;
        __stcs(&out[(size_t)(tbase + k) * N + n], o);
    }
}

// ---------------------------------------------------------------------------
extern "C" void kernel_launch(void* const* d_in, const int* in_sizes, int n_in,
                              void* d_out, int out_size) {
    const float* x  = (const float*)d_in[0];
    const float* t  = (const float*)d_in[1];
    const float* M0 = (const float*)d_in[2];
    const float* W1 = (const float*)d_in[3];
    const float* b1 = (const float*)d_in[4];
    const float* W2 = (const float*)d_in[5];
    const float* b2 = (const float*)d_in[6];
    const float* W3 = (const float*)d_in[7];
    const float* b3 = (const float*)d_in[8];
    float* out = (float*)d_out;

    int N = in_sizes[0] / 4;
    int T = in_sizes[1];    // <= PB*SPB (2048)

    static bool attr_set = false;
    if (!attr_set) {
        cudaFuncSetAttribute(prep_kernel,
                             cudaFuncAttributeMaxDynamicSharedMemorySize,
                             W2_BYTES);
        attr_set = true;
    }

    prep_kernel<<<PB, NTH, W2_BYTES>>>(t, M0, W1, b1, W2, b2, W3, b3, T);

    cudaLaunchConfig_t cfg = {};
    cfg.gridDim  = dim3((N + 255) / 256, (T + TT - 1) / TT, 1);
    cfg.blockDim = dim3(256, 1, 1);
    cfg.dynamicSmemBytes = 0;
    cfg.stream = 0;
    cudaLaunchAttribute attrs[1];
    attrs[0].id = cudaLaunchAttributeProgrammaticStreamSerialization;
    attrs[0].val.programmaticStreamSerializationAllowed = 1;
    cfg.attrs = attrs;
    cfg.numAttrs = 1;

    cudaLaunchKernelEx(&cfg, apply_kernel, x, (float4*)out, N, T);
}

// round 17
// speedup vs baseline: 1.0462x; 1.0456x over previous
#include <cuda_runtime.h>
#include <cuda_pipeline.h>
#include <math.h>

#define PB   128          // time groups == prep blocks (all co-resident)
#define SPB  16           // steps per group; PB*SPB == 2048
#define NTH  512
#define W2_BYTES (128 * 128 * sizeof(float))

__device__ float g_csum[16 * PB];      // per-group per-component sums
__device__ unsigned g_flag[PB];        // csum epoch flags (replay-safe)
__device__ float g_E[PB * SPB * 16];   // expm(cumsum)

__device__ __forceinline__ float tanh_fast(float v) {
    float y;
    asm("tanh.approx.f32 %0, %1;" : "=f"(y) : "f"(v));
    return y;
}

// ---------------------------------------------------------------------------
// Merged prep (R14 structure): MLP -> A (SMEM) -> csum+flag -> wait preds ->
// offsets -> scan -> expm -> g_E -> PDL trigger at END.
// New: cp.async W2/W3 staging overlapped with layer 1; split-K layer 3.
// ---------------------------------------------------------------------------
__global__ void __launch_bounds__(NTH, 1)
prep_kernel(const float* __restrict__ t,
            const float* __restrict__ M0,
            const float* __restrict__ W1, const float* __restrict__ b1,
            const float* __restrict__ W2, const float* __restrict__ b2,
            const float* __restrict__ W3, const float* __restrict__ b3,
            int T) {
    int b   = blockIdx.x;
    int tid = threadIdx.x;

    extern __shared__ float W2s[];   // 64 KB

    __shared__ float h1s[SPB * 128];
    __shared__ float h2s[SPB * 128];
    __shared__ float W3s[128 * 16];
    __shared__ float tavg[SPB], dts[SPB];
    __shared__ float As[SPB * 16];      // [s][p] A, then cumsum
    __shared__ float Es[SPB * 16];      // expm results
    __shared__ float L3p[SPB * 16];     // layer-3 partial sums (upper k half)
    __shared__ unsigned target_sh;

    if (tid == 0) target_sh = atomicAdd(&g_flag[b], 0u) + 1u;

    // async-stage W2 (64 KB) + W3 (8 KB) — overlapped with layer 1 below
    {
#pragma unroll
        for (int idx = tid; idx < 128 * 32; idx += NTH)
            __pipeline_memcpy_async((float4*)W2s + idx,
                                    (const float4*)W2 + idx, 16);
        for (int idx = tid; idx < 128 * 4; idx += NTH)
            __pipeline_memcpy_async((float4*)W3s + idx,
                                    (const float4*)W3 + idx, 16);
        __pipeline_commit();
    }

    if (tid < SPB) {
        int i = b * SPB + tid;
        float tc = (i < T) ? t[i] : 1.0f;
        float tp = (i == 0) ? 0.0f : ((i - 1 < T) ? t[i - 1] : 1.0f);
        dts[tid]  = tc - tp;
        tavg[tid] = 0.5f * (tc + tp);
    }
    __syncthreads();   // tavg/dts ready

    // layer 1 (independent of W2/W3 — overlaps the cp.async)
    for (int idx = tid; idx < SPB * 128; idx += NTH) {
        int s = idx >> 7, k = idx & 127;
        h1s[idx] = tanh_fast(tavg[s] * W1[k] + b1[k]);
    }
    __pipeline_wait_prior(0);
    __syncthreads();   // h1s + W2s + W3s ready

    // layer 2: thread = output j (tid&127), step group (tid>>7)*4
    {
        int j  = tid & 127;
        int sg = (tid >> 7) * 4;
        float bb = b2[j];
        float a0 = bb, a1 = bb, a2 = bb, a3 = bb;
#pragma unroll 8
        for (int k = 0; k < 128; k++) {
            float w = W2s[k * 128 + j];
            a0 = fmaf(w, h1s[(sg + 0) * 128 + k], a0);
            a1 = fmaf(w, h1s[(sg + 1) * 128 + k], a1);
            a2 = fmaf(w, h1s[(sg + 2) * 128 + k], a2);
            a3 = fmaf(w, h1s[(sg + 3) * 128 + k], a3);
        }
        h2s[(sg + 0) * 128 + j] = tanh_fast(a0);
        h2s[(sg + 1) * 128 + j] = tanh_fast(a1);
        h2s[(sg + 2) * 128 + j] = tanh_fast(a2);
        h2s[(sg + 3) * 128 + j] = tanh_fast(a3);
    }
    __syncthreads();

    // layer 3 split-K: all 512 threads; half = outputs x k[0:64),
    // other half = outputs x k[64:128) into L3p; then combine.
    {
        int o  = tid & 255;          // output index: s = o>>4, p = o&15
        int hi = tid >> 8;           // 0: low k half, 1: high k half
        int s = o >> 4;
        int p = o & 15;
        int k0 = hi * 64;
        float a0 = 0.f, a1 = 0.f, a2 = 0.f, a3 = 0.f;
#pragma unroll 8
        for (int k = k0; k < k0 + 64; k += 4) {
            a0 = fmaf(h2s[s * 128 + k + 0], W3s[(k + 0) * 16 + p], a0);
            a1 = fmaf(h2s[s * 128 + k + 1], W3s[(k + 1) * 16 + p], a1);
            a2 = fmaf(h2s[s * 128 + k + 2], W3s[(k + 2) * 16 + p], a2);
            a3 = fmaf(h2s[s * 128 + k + 3], W3s[(k + 3) * 16 + p], a3);
        }
        float part = (a0 + a1) + (a2 + a3);
        if (hi) L3p[o] = part;
        __syncthreads();
        if (!hi) As[o] = (part + L3p[o] + b3[p] + M0[p]) * dts[s];
    }
    __syncthreads();

    // publish chunk sums + epoch flag
    if (tid < 16) {
        int c = tid;
        float sum = 0.0f;
#pragma unroll
        for (int e = 0; e < SPB; e++) {
            int i = b * SPB + e;
            if (i < T) sum += As[e * 16 + c];
        }
        g_csum[c * PB + b] = sum;
    }
    __syncthreads();
    unsigned target = target_sh;
    if (tid == 0) {
        __threadfence();
        atomicExch(&g_flag[b], target);
    }

    // wait for predecessors 0..b-1
    if (tid < b) {
        while (atomicAdd(&g_flag[tid], 0u) < target) { }
    }
    __syncthreads();
    __threadfence();

    // offsets
    __shared__ float off[16];
    {
        int c = tid >> 4, l = tid & 15;
        if (c < 16) {
            float v = 0.0f;
            for (int q = l; q < b; q += 16) v += g_csum[c * PB + q];
            v += __shfl_down_sync(0xffffffffu, v, 8);
            v += __shfl_down_sync(0xffffffffu, v, 4);
            v += __shfl_down_sync(0xffffffffu, v, 2);
            v += __shfl_down_sync(0xffffffffu, v, 1);
            if (l == 0) off[c] = v;
        }
    }
    __syncthreads();

    // local inclusive scan
    if (tid < 16) {
        int c = tid;
        float run = off[c];
#pragma unroll
        for (int e = 0; e < SPB; e++) {
            run += As[e * 16 + c];
            As[e * 16 + c] = run;
        }
    }
    __syncthreads();

    // expm: threads 0..15, one matrix each -> Es
    if (tid < SPB) {
        float a[16];
#pragma unroll
        for (int p = 0; p < 16; p++) a[p] = As[tid * 16 + p];

        float nrm = 0.0f;
#pragma unroll
        for (int r = 0; r < 4; r++) {
            float rs = fabsf(a[r*4]) + fabsf(a[r*4+1]) + fabsf(a[r*4+2]) + fabsf(a[r*4+3]);
            nrm = fmaxf(nrm, rs);
        }
        int sq = 0;
        while (nrm > 0.5f && sq < 40) { nrm *= 0.5f; sq++; }
        float sc = ldexpf(1.0f, -sq);
#pragma unroll
        for (int p = 0; p < 16; p++) a[p] *= sc;

        float P[16], E[16];
#pragma unroll
        for (int p = 0; p < 16; p++) { P[p] = a[p]; E[p] = a[p]; }
#pragma unroll
        for (int d = 0; d < 4; d++) E[d * 5] += 1.0f;

        for (int k = 2; k <= 10; k++) {
            float Q[16];
            float inv = 1.0f / (float)k;
#pragma unroll
            for (int r = 0; r < 4; r++)
#pragma unroll
                for (int c = 0; c < 4; c++)
                    Q[r*4+c] = (P[r*4+0]*a[0*4+c] + P[r*4+1]*a[1*4+c]
                              + P[r*4+2]*a[2*4+c] + P[r*4+3]*a[3*4+c]) * inv;
#pragma unroll
            for (int p = 0; p < 16; p++) { P[p] = Q[p]; E[p] += Q[p]; }
        }
        for (int q = 0; q < sq; q++) {
            float Q[16];
#pragma unroll
            for (int r = 0; r < 4; r++)
#pragma unroll
                for (int c = 0; c < 4; c++)
                    Q[r*4+c] = E[r*4+0]*E[0*4+c] + E[r*4+1]*E[1*4+c]
                             + E[r*4+2]*E[2*4+c] + E[r*4+3]*E[3*4+c];
#pragma unroll
            for (int p = 0; p < 16; p++) E[p] = Q[p];
        }
#pragma unroll
        for (int p = 0; p < 16; p++) Es[tid * 16 + p] = E[p];
    }
    __syncthreads();

    // coalesced g_E write
    if (tid < SPB * 16) {
        int i = b * SPB + (tid >> 4);
        if (i < T) g_E[i * 16 + (tid & 15)] = Es[tid];
    }
    __syncthreads();
    __threadfence();

    asm volatile("griddepcontrol.launch_dependents;");
}

// ---------------------------------------------------------------------------
// Apply (heavy, R14 exact): out[t,n,:] = E[t] @ x[n,:]. All __stcs.
// ---------------------------------------------------------------------------
#define TT 16
__global__ void __launch_bounds__(256)
apply_kernel(const float* __restrict__ x,
             float4* __restrict__ out,
             int N, int T) {
    int tbase = blockIdx.y * TT;
    int n = blockIdx.x * blockDim.x + threadIdx.x;

    float4 xv = make_float4(0.f, 0.f, 0.f, 0.f);
    if (n < N) xv = __ldg((const float4*)x + n);

    asm volatile("griddepcontrol.wait;" ::: "memory");

    __shared__ float Es[TT * 16];
    int nt = T - tbase; if (nt > TT) nt = TT;
    if (threadIdx.x < nt * 16) Es[threadIdx.x] = g_E[tbase * 16 + threadIdx.x];
    __syncthreads();

    if (n >= N) return;

#pragma unroll
    for (int k = 0; k < TT; k++) {
        if (k >= nt) break;
        const float* e = &Es[k * 16];
        float4 o;
        o.x = e[0]  * xv.x + e[1]  * xv.y + e[2]  * xv.z + e[3]  * xv.w;
        o.y = e[4]  * xv.x + e[5]  * xv.y + e[6]  * xv.z + e[7]  * xv.w;
        o.z = e[8]  * xv.x + e[9]  * xv.y + e[10] * xv.z + e[11] * xv.w;
        o.w = e[12] * xv.x + e[13] * xv.y + e[14] * xv.z + e[15] * xv.w;
        __stcs(&out[(size_t)(tbase + k) * N + n], o);
    }
}

// ---------------------------------------------------------------------------
extern "C" void kernel_launch(void* const* d_in, const int* in_sizes, int n_in,
                              void* d_out, int out_size) {
    const float* x  = (const float*)d_in[0];
    const float* t  = (const float*)d_in[1];
    const float* M0 = (const float*)d_in[2];
    const float* W1 = (const float*)d_in[3];
    const float* b1 = (const float*)d_in[4];
    const float* W2 = (const float*)d_in[5];
    const float* b2 = (const float*)d_in[6];
    const float* W3 = (const float*)d_in[7];
    const float* b3 = (const float*)d_in[8];
    float* out = (float*)d_out;

    int N = in_sizes[0] / 4;
    int T = in_sizes[1];    // <= PB*SPB (2048)

    static bool attr_set = false;
    if (!attr_set) {
        cudaFuncSetAttribute(prep_kernel,
                             cudaFuncAttributeMaxDynamicSharedMemorySize,
                             W2_BYTES);
        attr_set = true;
    }

    prep_kernel<<<PB, NTH, W2_BYTES>>>(t, M0, W1, b1, W2, b2, W3, b3, T);

    cudaLaunchConfig_t cfg = {};
    cfg.gridDim  = dim3((N + 255) / 256, (T + TT - 1) / TT, 1);
    cfg.blockDim = dim3(256, 1, 1);
    cfg.dynamicSmemBytes = 0;
    cfg.stream = 0;
    cudaLaunchAttribute attrs[1];
    attrs[0].id = cudaLaunchAttributeProgrammaticStreamSerialization;
    attrs[0].val.programmaticStreamSerializationAllowed = 1;
    cfg.attrs = attrs;
    cfg.numAttrs = 1;

    cudaLaunchKernelEx(&cfg, apply_kernel, x, (float4*)out, N, T);
}